// round 14
// baseline (speedup 1.0000x reference)
#include <cuda_runtime.h>
#include <cuda_bf16.h>
#include <cstdint>

// ============================================================================
// RBF kernel: out[m][n] = exp(-(||x_m||^2 + ||y_n||^2 - 2 x_m.y_n)), gamma=1
// x, y: 8192 x 64 fp32.  out: 8192 x 8192 fp32.
//
// R14: A fragments hoisted out of the n-tile loop (x tile is tile-invariant;
// was reloaded 4x via LDSM).  Otherwise identical to validated R13: single
// bf16 GEMM, log-domain ex2 epilogue, PERM16 STG.cs.128 stores, cp.async
// double-buffered 4-tile walk.
// ============================================================================

#define NROWS 8192
#define DDIM  64

__device__ __nv_bfloat16 g_xh[NROWS * DDIM];
__device__ __nv_bfloat16 g_yh[NROWS * DDIM];
__device__ float g_xb[NROWS];   // -log2e * ||x_row||^2
__device__ float g_yb[NROWS];   // -log2e * ||y_row||^2

__device__ __forceinline__ uint32_t smem_u32(const void* p) {
    uint32_t a;
    asm("{ .reg .u64 t; cvta.to.shared.u64 t, %1; cvt.u32.u64 %0, t; }"
        : "=r"(a) : "l"(p));
    return a;
}

#define SWZ128(off) ((off) ^ (((off) >> 3) & 0x70))

// Column permutation within each 16-col group: logical col l sits at physical
// accumulator col perm16(l).  Thread q (= lane&3) then owns logical columns
// 4q..4q+3 -> float4 stores.
#define PERM16(v) ((((v) >> 1) & 1) << 3 | (((v) >> 2) & 3) << 1 | ((v) & 1))

#define LDSM_X4(r0, r1, r2, r3, addr)                                          \
    asm volatile("ldmatrix.sync.aligned.m8n8.x4.shared.b16 {%0,%1,%2,%3}, [%4];" \
                 : "=r"(r0), "=r"(r1), "=r"(r2), "=r"(r3) : "r"(addr))

#define MMA_BF16(c, a, b0, b1)                                                 \
    asm volatile(                                                              \
        "mma.sync.aligned.m16n8k16.row.col.f32.bf16.bf16.f32 "                 \
        "{%0,%1,%2,%3}, {%4,%5,%6,%7}, {%8,%9}, {%0,%1,%2,%3};"                \
        : "+f"((c)[0]), "+f"((c)[1]), "+f"((c)[2]), "+f"((c)[3])               \
        : "r"((a)[0]), "r"((a)[1]), "r"((a)[2]), "r"((a)[3]),                  \
          "r"(b0), "r"(b1))

#define CP_ASYNC16(dst, src)                                                   \
    asm volatile("cp.async.cg.shared.global [%0], [%1], 16;"                   \
                 :: "r"(dst), "l"(src))
#define CP_COMMIT()  asm volatile("cp.async.commit_group;" ::: "memory")
#define CP_WAIT0()   asm volatile("cp.async.wait_group 0;" ::: "memory")

#define STG_CS_128(ptr, r)                                                     \
    asm volatile("st.global.cs.v4.f32 [%0], {%1,%2,%3,%4};"                    \
                 :: "l"(ptr), "f"((r).x), "f"((r).y), "f"((r).z), "f"((r).w)   \
                 : "memory")

// ---------------------------------------------------------------------------
// Prologue: bf16 cast + log-domain row norms. One warp per row.
// ---------------------------------------------------------------------------
__global__ void rbf_split(const float* __restrict__ x,
                          const float* __restrict__ y) {
    int warp = (blockIdx.x * blockDim.x + threadIdx.x) >> 5;
    int lane = threadIdx.x & 31;
    if (warp >= 2 * NROWS) return;
    bool isx = warp < NROWS;
    int row = isx ? warp : warp - NROWS;
    const float* src = (isx ? x : y) + (size_t)row * DDIM;
    __nv_bfloat16* hi = (isx ? g_xh : g_yh) + (size_t)row * DDIM;
    float s = 0.0f;
#pragma unroll
    for (int i = 0; i < 2; i++) {
        int c = lane + i * 32;
        float v = src[c];
        hi[c] = __float2bfloat16(v);
        s = fmaf(v, v, s);
    }
#pragma unroll
    for (int o = 16; o; o >>= 1) s += __shfl_xor_sync(0xFFFFFFFFu, s, o);
    if (lane == 0)
        (isx ? g_xb : g_yb)[row] = s * (-1.4426950408889634f);
}

// ---------------------------------------------------------------------------
// Main: CTA = 128 m-rows x 4 n-tiles of 128.  256 threads = 8 warps (4m x 2n),
// warp tile 32x64 per n-tile.  y tiles double-buffered via cp.async.
// ---------------------------------------------------------------------------
#define SM_XB    0                      // 128 floats (512 B)
#define SM_YB_0  512                    // 128 floats (buffer 0)
#define SM_YB_1  1024                   // 128 floats (buffer 1)
#define SM_XT    2048                   // x tile: 16 KB (1024-aligned)
#define SM_YT0   (SM_XT + 16384)        // y tile buf0 (1024-aligned)
#define SM_YT1   (SM_YT0 + 16384)       // y tile buf1
#define SMEM_TOTAL (SM_YT1 + 16384)     // 51200 B

#define NTILES 4

__global__ void __launch_bounds__(256, 2)
rbf_main(float* __restrict__ out) {
    extern __shared__ char smem[];
    const uint32_t sb = smem_u32(smem);
    const int tid = threadIdx.x;
    const int wid = tid >> 5;
    const int lane = tid & 31;
    const int warp_m = wid & 3;          // m offset *32
    const int warp_n = wid >> 2;         // n offset *64
    const int m_base = blockIdx.x << 7;
    const int n_grp  = blockIdx.y;       // group of 4 n-tiles

    // ---- x tile (plain LDG/STS, once per CTA) + xb
    {
        const uint4* xh = (const uint4*)(g_xh + (size_t)m_base * DDIM);
#pragma unroll
        for (int idx = tid; idx < 1024; idx += 256) {
            uint32_t sw = SWZ128((uint32_t)idx * 16u);
            *(uint4*)(smem + SM_XT + sw) = xh[idx];
        }
        if (tid < 128) ((float*)(smem + SM_XB))[tid] = g_xb[m_base + tid];
    }

    // ---- prefetch y tile 0 + yb[0] via cp.async (PERM16 row order for tile)
    {
        const int n_base0 = (n_grp * NTILES) << 7;
        const uint4* yh = (const uint4*)(g_yh + (size_t)n_base0 * DDIM);
#pragma unroll
        for (int idx = tid; idx < 1024; idx += 256) {
            uint32_t row = (uint32_t)idx >> 3, cc = (uint32_t)idx & 7;
            uint32_t prow = (row & 0x70u) | (uint32_t)PERM16(row & 15u);
            uint32_t dsw = SWZ128(prow * 128u + cc * 16u);
            CP_ASYNC16(sb + SM_YT0 + dsw, yh + idx);
        }
        if (tid < 32)
            CP_ASYNC16(sb + SM_YB_0 + tid * 16u,
                       (const uint4*)(g_yb + n_base0) + tid);
        CP_COMMIT();
    }
    __syncthreads();   // x tile + xb visible CTA-wide

    const int grp = lane >> 3, rl = lane & 7;
    const uint32_t a_row  = (uint32_t)(warp_m * 32 + (grp & 1) * 8 + rl);
    const uint32_t a_koff = (uint32_t)((grp >> 1) * 8);
    const uint32_t b_row  = (uint32_t)(warp_n * 64 + ((grp >> 1) & 1) * 8 + rl);
    const uint32_t b_koff = (uint32_t)((grp & 1) * 8);
    const int q = lane & 3;
    const float TWO_L2E = 2.8853900817779268f;   // 2*log2(e)

    // ---- A fragments: tile-invariant -> load ONCE per CTA (32 regs).
    uint32_t ah[4][2][4];
#pragma unroll
    for (int ks = 0; ks < 4; ks++)
#pragma unroll
        for (int mt = 0; mt < 2; mt++) {
            uint32_t off = (a_row + (uint32_t)(mt * 16)) * 128u
                         + ((uint32_t)(ks * 16) + a_koff) * 2u;
            LDSM_X4(ah[ks][mt][0], ah[ks][mt][1], ah[ks][mt][2],
                    ah[ks][mt][3], sb + SM_XT + SWZ128(off));
        }

    // Per-row hoists (tile-invariant): xb values + output row pointers.
    const float* xbs = (const float*)(smem + SM_XB);
    float xv[2][2];
    float* orow[2][2];
#pragma unroll
    for (int mt = 0; mt < 2; mt++)
#pragma unroll
        for (int rh = 0; rh < 2; rh++) {
            const int row = warp_m * 32 + mt * 16 + rh * 8 + (lane >> 2);
            xv[mt][rh] = xbs[row];
            orow[mt][rh] = out + (size_t)(m_base + row) * NROWS
                               + (size_t)((n_grp * NTILES) << 7)
                               + (size_t)(warp_n * 64 + 4 * q);
        }

#pragma unroll
    for (int t = 0; t < NTILES; t++) {
        const uint32_t yb  = (t & 1) ? SM_YT1 : SM_YT0;
        const uint32_t ybv = (t & 1) ? SM_YB_1 : SM_YB_0;

        // Wait current y buffer, make visible CTA-wide.
        CP_WAIT0();
        __syncthreads();

        // Prefetch next tile into the OTHER buffer right away.
        if (t + 1 < NTILES) {
            const uint32_t ybn  = (t & 1) ? SM_YT0 : SM_YT1;
            const uint32_t ybvn = (t & 1) ? SM_YB_0 : SM_YB_1;
            const int n_next = (n_grp * NTILES + t + 1) << 7;
            const uint4* yh = (const uint4*)(g_yh + (size_t)n_next * DDIM);
#pragma unroll
            for (int idx = tid; idx < 1024; idx += 256) {
                uint32_t row = (uint32_t)idx >> 3, cc = (uint32_t)idx & 7;
                uint32_t prow = (row & 0x70u) | (uint32_t)PERM16(row & 15u);
                uint32_t dsw = SWZ128(prow * 128u + cc * 16u);
                CP_ASYNC16(sb + ybn + dsw, yh + idx);
            }
            if (tid < 32)
                CP_ASYNC16(sb + ybvn + tid * 16u,
                           (const uint4*)(g_yb + n_next) + tid);
            CP_COMMIT();
        }

        const float* ybs = (const float*)(smem + ybv);

        // ---- np-outer: MMA a 128x32 slab, then immediately its epilogue.
#pragma unroll
        for (int np = 0; np < 4; np++) {
            uint32_t bh[4][4];
#pragma unroll
            for (int ks = 0; ks < 4; ks++) {
                uint32_t off = (b_row + (uint32_t)(np * 16)) * 128u
                             + ((uint32_t)(ks * 16) + b_koff) * 2u;
                LDSM_X4(bh[ks][0], bh[ks][1], bh[ks][2], bh[ks][3],
                        sb + yb + SWZ128(off));
            }

            float c[2][2][4];
#pragma unroll
            for (int a = 0; a < 2; a++)
#pragma unroll
                for (int d = 0; d < 2; d++)
#pragma unroll
                    for (int e = 0; e < 4; e++) c[a][d][e] = 0.0f;

#pragma unroll
            for (int ks = 0; ks < 4; ks++) {
#pragma unroll
                for (int mt = 0; mt < 2; mt++)
                    MMA_BF16(c[mt][0], ah[ks][mt], bh[ks][0], bh[ks][1]);
#pragma unroll
                for (int mt = 0; mt < 2; mt++)
                    MMA_BF16(c[mt][1], ah[ks][mt], bh[ks][2], bh[ks][3]);
            }

            // Log-domain epilogue: out = 2^( xb + yb + 2*log2e*d ).
            const float4 ybq =
                *(const float4*)(ybs + warp_n * 64 + np * 16 + 4 * q);
#pragma unroll
            for (int mt = 0; mt < 2; mt++) {
#pragma unroll
                for (int rh = 0; rh < 2; rh++) {
                    const float xb2 = xv[mt][rh];
                    float u0 = fmaf(c[mt][0][rh * 2 + 0], TWO_L2E, xb2 + ybq.x);
                    float u1 = fmaf(c[mt][0][rh * 2 + 1], TWO_L2E, xb2 + ybq.y);
                    float u2 = fmaf(c[mt][1][rh * 2 + 0], TWO_L2E, xb2 + ybq.z);
                    float u3 = fmaf(c[mt][1][rh * 2 + 1], TWO_L2E, xb2 + ybq.w);
                    float4 r;
                    asm("ex2.approx.f32 %0, %1;" : "=f"(r.x) : "f"(u0));
                    asm("ex2.approx.f32 %0, %1;" : "=f"(r.y) : "f"(u1));
                    asm("ex2.approx.f32 %0, %1;" : "=f"(r.z) : "f"(u2));
                    asm("ex2.approx.f32 %0, %1;" : "=f"(r.w) : "f"(u3));
                    STG_CS_128(orow[mt][rh] + t * 128 + np * 16, r);
                }
            }
        }
    }
}

// ---------------------------------------------------------------------------
extern "C" void kernel_launch(void* const* d_in, const int* in_sizes, int n_in,
                              void* d_out, int out_size) {
    const float* x = (const float*)d_in[0];
    const float* y = (const float*)d_in[1];
    float* out = (float*)d_out;

    cudaFuncSetAttribute(rbf_main,
                         cudaFuncAttributeMaxDynamicSharedMemorySize,
                         SMEM_TOTAL);

    rbf_split<<<2048, 256>>>(x, y);

    dim3 grid(NROWS / 128, NROWS / (128 * NTILES));  // 64 x 16
    rbf_main<<<grid, 256, SMEM_TOTAL>>>(out);
}

// round 17
// speedup vs baseline: 1.1476x; 1.1476x over previous
#include <cuda_runtime.h>
#include <cuda_bf16.h>
#include <cstdint>

// ============================================================================
// RBF kernel: out[m][n] = exp(-(||x_m||^2 + ||y_n||^2 - 2 x_m.y_n)), gamma=1
// x, y: 8192 x 64 fp32.  out: 8192 x 8192 fp32.
//
// R15: NTILES 4 -> 2 (grid 2048 CTAs): halves CTA duration so the final
// partial wave exposes far less idle SM time (3.46 coarse waves -> 6.9 fine
// waves).  Pipeline otherwise identical to validated R13/R14: single bf16
// GEMM, log-domain ex2 epilogue, PERM16 STG.cs.128, cp.async double buffer.
// ============================================================================

#define NROWS 8192
#define DDIM  64

__device__ __nv_bfloat16 g_xh[NROWS * DDIM];
__device__ __nv_bfloat16 g_yh[NROWS * DDIM];
__device__ float g_xb[NROWS];   // -log2e * ||x_row||^2
__device__ float g_yb[NROWS];   // -log2e * ||y_row||^2

__device__ __forceinline__ uint32_t smem_u32(const void* p) {
    uint32_t a;
    asm("{ .reg .u64 t; cvta.to.shared.u64 t, %1; cvt.u32.u64 %0, t; }"
        : "=r"(a) : "l"(p));
    return a;
}

#define SWZ128(off) ((off) ^ (((off) >> 3) & 0x70))

// Column permutation within each 16-col group: logical col l sits at physical
// accumulator col perm16(l).  Thread q (= lane&3) then owns logical columns
// 4q..4q+3 -> float4 stores.
#define PERM16(v) ((((v) >> 1) & 1) << 3 | (((v) >> 2) & 3) << 1 | ((v) & 1))

#define LDSM_X4(r0, r1, r2, r3, addr)                                          \
    asm volatile("ldmatrix.sync.aligned.m8n8.x4.shared.b16 {%0,%1,%2,%3}, [%4];" \
                 : "=r"(r0), "=r"(r1), "=r"(r2), "=r"(r3) : "r"(addr))

#define MMA_BF16(c, a, b0, b1)                                                 \
    asm volatile(                                                              \
        "mma.sync.aligned.m16n8k16.row.col.f32.bf16.bf16.f32 "                 \
        "{%0,%1,%2,%3}, {%4,%5,%6,%7}, {%8,%9}, {%0,%1,%2,%3};"                \
        : "+f"((c)[0]), "+f"((c)[1]), "+f"((c)[2]), "+f"((c)[3])               \
        : "r"((a)[0]), "r"((a)[1]), "r"((a)[2]), "r"((a)[3]),                  \
          "r"(b0), "r"(b1))

#define CP_ASYNC16(dst, src)                                                   \
    asm volatile("cp.async.cg.shared.global [%0], [%1], 16;"                   \
                 :: "r"(dst), "l"(src))
#define CP_COMMIT()  asm volatile("cp.async.commit_group;" ::: "memory")
#define CP_WAIT0()   asm volatile("cp.async.wait_group 0;" ::: "memory")

#define STG_CS_128(ptr, r)                                                     \
    asm volatile("st.global.cs.v4.f32 [%0], {%1,%2,%3,%4};"                    \
                 :: "l"(ptr), "f"((r).x), "f"((r).y), "f"((r).z), "f"((r).w)   \
                 : "memory")

// ---------------------------------------------------------------------------
// Prologue: bf16 cast + log-domain row norms. One warp per row.
// ---------------------------------------------------------------------------
__global__ void rbf_split(const float* __restrict__ x,
                          const float* __restrict__ y) {
    int warp = (blockIdx.x * blockDim.x + threadIdx.x) >> 5;
    int lane = threadIdx.x & 31;
    if (warp >= 2 * NROWS) return;
    bool isx = warp < NROWS;
    int row = isx ? warp : warp - NROWS;
    const float* src = (isx ? x : y) + (size_t)row * DDIM;
    __nv_bfloat16* hi = (isx ? g_xh : g_yh) + (size_t)row * DDIM;
    float s = 0.0f;
#pragma unroll
    for (int i = 0; i < 2; i++) {
        int c = lane + i * 32;
        float v = src[c];
        hi[c] = __float2bfloat16(v);
        s = fmaf(v, v, s);
    }
#pragma unroll
    for (int o = 16; o; o >>= 1) s += __shfl_xor_sync(0xFFFFFFFFu, s, o);
    if (lane == 0)
        (isx ? g_xb : g_yb)[row] = s * (-1.4426950408889634f);
}

// ---------------------------------------------------------------------------
// Main: CTA = 128 m-rows x 2 n-tiles of 128.  256 threads = 8 warps (4m x 2n),
// warp tile 32x64 per n-tile.  y tiles double-buffered via cp.async.
// ---------------------------------------------------------------------------
#define SM_XB    0                      // 128 floats (512 B)
#define SM_YB_0  512                    // 128 floats (buffer 0)
#define SM_YB_1  1024                   // 128 floats (buffer 1)
#define SM_XT    2048                   // x tile: 16 KB (1024-aligned)
#define SM_YT0   (SM_XT + 16384)        // y tile buf0 (1024-aligned)
#define SM_YT1   (SM_YT0 + 16384)       // y tile buf1
#define SMEM_TOTAL (SM_YT1 + 16384)     // 51200 B

#define NTILES 2

__global__ void __launch_bounds__(256, 2)
rbf_main(float* __restrict__ out) {
    extern __shared__ char smem[];
    const uint32_t sb = smem_u32(smem);
    const int tid = threadIdx.x;
    const int wid = tid >> 5;
    const int lane = tid & 31;
    const int warp_m = wid & 3;          // m offset *32
    const int warp_n = wid >> 2;         // n offset *64
    const int m_base = blockIdx.x << 7;
    const int n_grp  = blockIdx.y;       // group of NTILES n-tiles

    // ---- x tile (plain LDG/STS, once per CTA) + xb
    {
        const uint4* xh = (const uint4*)(g_xh + (size_t)m_base * DDIM);
#pragma unroll
        for (int idx = tid; idx < 1024; idx += 256) {
            uint32_t sw = SWZ128((uint32_t)idx * 16u);
            *(uint4*)(smem + SM_XT + sw) = xh[idx];
        }
        if (tid < 128) ((float*)(smem + SM_XB))[tid] = g_xb[m_base + tid];
    }

    // ---- prefetch y tile 0 + yb[0] via cp.async (PERM16 row order for tile)
    {
        const int n_base0 = (n_grp * NTILES) << 7;
        const uint4* yh = (const uint4*)(g_yh + (size_t)n_base0 * DDIM);
#pragma unroll
        for (int idx = tid; idx < 1024; idx += 256) {
            uint32_t row = (uint32_t)idx >> 3, cc = (uint32_t)idx & 7;
            uint32_t prow = (row & 0x70u) | (uint32_t)PERM16(row & 15u);
            uint32_t dsw = SWZ128(prow * 128u + cc * 16u);
            CP_ASYNC16(sb + SM_YT0 + dsw, yh + idx);
        }
        if (tid < 32)
            CP_ASYNC16(sb + SM_YB_0 + tid * 16u,
                       (const uint4*)(g_yb + n_base0) + tid);
        CP_COMMIT();
    }
    __syncthreads();   // x tile + xb visible CTA-wide

    const int grp = lane >> 3, rl = lane & 7;
    const uint32_t a_row  = (uint32_t)(warp_m * 32 + (grp & 1) * 8 + rl);
    const uint32_t a_koff = (uint32_t)((grp >> 1) * 8);
    const uint32_t b_row  = (uint32_t)(warp_n * 64 + ((grp >> 1) & 1) * 8 + rl);
    const uint32_t b_koff = (uint32_t)((grp & 1) * 8);
    const int q = lane & 3;
    const float TWO_L2E = 2.8853900817779268f;   // 2*log2(e)

    // ---- A fragments: tile-invariant -> load ONCE per CTA (32 regs).
    uint32_t ah[4][2][4];
#pragma unroll
    for (int ks = 0; ks < 4; ks++)
#pragma unroll
        for (int mt = 0; mt < 2; mt++) {
            uint32_t off = (a_row + (uint32_t)(mt * 16)) * 128u
                         + ((uint32_t)(ks * 16) + a_koff) * 2u;
            LDSM_X4(ah[ks][mt][0], ah[ks][mt][1], ah[ks][mt][2],
                    ah[ks][mt][3], sb + SM_XT + SWZ128(off));
        }

    // Per-row hoists (tile-invariant): xb values + output row pointers.
    const float* xbs = (const float*)(smem + SM_XB);
    float xv[2][2];
    float* orow[2][2];
#pragma unroll
    for (int mt = 0; mt < 2; mt++)
#pragma unroll
        for (int rh = 0; rh < 2; rh++) {
            const int row = warp_m * 32 + mt * 16 + rh * 8 + (lane >> 2);
            xv[mt][rh] = xbs[row];
            orow[mt][rh] = out + (size_t)(m_base + row) * NROWS
                               + (size_t)((n_grp * NTILES) << 7)
                               + (size_t)(warp_n * 64 + 4 * q);
        }

#pragma unroll
    for (int t = 0; t < NTILES; t++) {
        const uint32_t yb  = (t & 1) ? SM_YT1 : SM_YT0;
        const uint32_t ybv = (t & 1) ? SM_YB_1 : SM_YB_0;

        // Wait current y buffer, make visible CTA-wide.
        CP_WAIT0();
        __syncthreads();

        // Prefetch next tile into the OTHER buffer right away.
        if (t + 1 < NTILES) {
            const uint32_t ybn  = (t & 1) ? SM_YT0 : SM_YT1;
            const uint32_t ybvn = (t & 1) ? SM_YB_0 : SM_YB_1;
            const int n_next = (n_grp * NTILES + t + 1) << 7;
            const uint4* yh = (const uint4*)(g_yh + (size_t)n_next * DDIM);
#pragma unroll
            for (int idx = tid; idx < 1024; idx += 256) {
                uint32_t row = (uint32_t)idx >> 3, cc = (uint32_t)idx & 7;
                uint32_t prow = (row & 0x70u) | (uint32_t)PERM16(row & 15u);
                uint32_t dsw = SWZ128(prow * 128u + cc * 16u);
                CP_ASYNC16(sb + ybn + dsw, yh + idx);
            }
            if (tid < 32)
                CP_ASYNC16(sb + ybvn + tid * 16u,
                           (const uint4*)(g_yb + n_next) + tid);
            CP_COMMIT();
        }

        const float* ybs = (const float*)(smem + ybv);

        // ---- np-outer: MMA a 128x32 slab, then immediately its epilogue.
#pragma unroll
        for (int np = 0; np < 4; np++) {
            uint32_t bh[4][4];
#pragma unroll
            for (int ks = 0; ks < 4; ks++) {
                uint32_t off = (b_row + (uint32_t)(np * 16)) * 128u
                             + ((uint32_t)(ks * 16) + b_koff) * 2u;
                LDSM_X4(bh[ks][0], bh[ks][1], bh[ks][2], bh[ks][3],
                        sb + yb + SWZ128(off));
            }

            float c[2][2][4];
#pragma unroll
            for (int a = 0; a < 2; a++)
#pragma unroll
                for (int d = 0; d < 2; d++)
#pragma unroll
                    for (int e = 0; e < 4; e++) c[a][d][e] = 0.0f;

#pragma unroll
            for (int ks = 0; ks < 4; ks++) {
#pragma unroll
                for (int mt = 0; mt < 2; mt++)
                    MMA_BF16(c[mt][0], ah[ks][mt], bh[ks][0], bh[ks][1]);
#pragma unroll
                for (int mt = 0; mt < 2; mt++)
                    MMA_BF16(c[mt][1], ah[ks][mt], bh[ks][2], bh[ks][3]);
            }

            // Log-domain epilogue: out = 2^( xb + yb + 2*log2e*d ).
            const float4 ybq =
                *(const float4*)(ybs + warp_n * 64 + np * 16 + 4 * q);
#pragma unroll
            for (int mt = 0; mt < 2; mt++) {
#pragma unroll
                for (int rh = 0; rh < 2; rh++) {
                    const float xb2 = xv[mt][rh];
                    float u0 = fmaf(c[mt][0][rh * 2 + 0], TWO_L2E, xb2 + ybq.x);
                    float u1 = fmaf(c[mt][0][rh * 2 + 1], TWO_L2E, xb2 + ybq.y);
                    float u2 = fmaf(c[mt][1][rh * 2 + 0], TWO_L2E, xb2 + ybq.z);
                    float u3 = fmaf(c[mt][1][rh * 2 + 1], TWO_L2E, xb2 + ybq.w);
                    float4 r;
                    asm("ex2.approx.f32 %0, %1;" : "=f"(r.x) : "f"(u0));
                    asm("ex2.approx.f32 %0, %1;" : "=f"(r.y) : "f"(u1));
                    asm("ex2.approx.f32 %0, %1;" : "=f"(r.z) : "f"(u2));
                    asm("ex2.approx.f32 %0, %1;" : "=f"(r.w) : "f"(u3));
                    STG_CS_128(orow[mt][rh] + t * 128 + np * 16, r);
                }
            }
        }
    }
}

// ---------------------------------------------------------------------------
extern "C" void kernel_launch(void* const* d_in, const int* in_sizes, int n_in,
                              void* d_out, int out_size) {
    const float* x = (const float*)d_in[0];
    const float* y = (const float*)d_in[1];
    float* out = (float*)d_out;

    cudaFuncSetAttribute(rbf_main,
                         cudaFuncAttributeMaxDynamicSharedMemorySize,
                         SMEM_TOTAL);

    rbf_split<<<2048, 256>>>(x, y);

    dim3 grid(NROWS / 128, NROWS / (128 * NTILES));  // 64 x 32
    rbf_main<<<grid, 256, SMEM_TOTAL>>>(out);
}